// round 4
// baseline (speedup 1.0000x reference)
#include <cuda_runtime.h>
#include <cuda_bf16.h>
#include <cstdint>

// out[row, :] = weight[indices[row], :]
// rows = 16384, row = 4096 bytes (1024 fp32).
// Bulk-async gather: per CTA, 8 rows loaded gmem->smem via cp.async.bulk
// (mbarrier complete_tx), then stored smem->gmem as two contiguous 16KB
// bulk stores. One issuing thread; DMA engine provides the MLP.

constexpr int ROWS_PER_CTA   = 8;
constexpr int ROW_BYTES      = 4096;
constexpr int GROUPS         = 2;
constexpr int ROWS_PER_GROUP = ROWS_PER_CTA / GROUPS;     // 4
constexpr int GROUP_BYTES    = ROWS_PER_GROUP * ROW_BYTES; // 16384

__global__ void __launch_bounds__(32)
gather_bulk_kernel(const int* __restrict__ indices,
                   const char* __restrict__ weight,
                   char* __restrict__ out)
{
    __shared__ alignas(128) char buf[ROWS_PER_CTA * ROW_BYTES];
    __shared__ alignas(8) unsigned long long mbar[GROUPS];
    __shared__ int sidx[ROWS_PER_CTA];

    const int tid = threadIdx.x;
    const size_t base_row = (size_t)blockIdx.x * ROWS_PER_CTA;

    if (tid < ROWS_PER_CTA)
        sidx[tid] = __ldg(&indices[base_row + tid]);

    const uint32_t smem_base = (uint32_t)__cvta_generic_to_shared(buf);
    const uint32_t mbar_base = (uint32_t)__cvta_generic_to_shared(&mbar[0]);

    if (tid == 0) {
        #pragma unroll
        for (int g = 0; g < GROUPS; g++)
            asm volatile("mbarrier.init.shared.b64 [%0], 1;"
                         :: "r"(mbar_base + g * 8) : "memory");
    }
    __syncwarp();

    if (tid == 0) {
        // Issue all gather loads up front (engine pipelines them).
        #pragma unroll
        for (int g = 0; g < GROUPS; g++) {
            const uint32_t m = mbar_base + g * 8;
            asm volatile("mbarrier.arrive.expect_tx.shared.b64 _, [%0], %1;"
                         :: "r"(m), "r"(GROUP_BYTES) : "memory");
            #pragma unroll
            for (int r = 0; r < ROWS_PER_GROUP; r++) {
                const int row = g * ROWS_PER_GROUP + r;
                const char* src = weight + (size_t)sidx[row] * ROW_BYTES;
                const uint32_t dst = smem_base + row * ROW_BYTES;
                asm volatile(
                    "cp.async.bulk.shared::cta.global.mbarrier::complete_tx::bytes "
                    "[%0], [%1], %2, [%3];"
                    :: "r"(dst), "l"(src), "r"(ROW_BYTES), "r"(m) : "memory");
            }
        }

        // Consume groups in order: wait, then bulk-store 16KB contiguous.
        char* dst_g = out + base_row * ROW_BYTES;
        #pragma unroll
        for (int g = 0; g < GROUPS; g++) {
            const uint32_t m = mbar_base + g * 8;
            asm volatile(
                "{\n\t"
                ".reg .pred P1;\n\t"
                "WAIT_%=:\n\t"
                "mbarrier.try_wait.parity.shared.b64 P1, [%0], 0;\n\t"
                "@P1 bra DONE_%=;\n\t"
                "bra WAIT_%=;\n\t"
                "DONE_%=:\n\t"
                "}"
                :: "r"(m) : "memory");
            asm volatile(
                "cp.async.bulk.global.shared::cta.bulk_group [%0], [%1], %2;"
                :: "l"(dst_g + (size_t)g * GROUP_BYTES),
                   "r"(smem_base + g * GROUP_BYTES),
                   "r"(GROUP_BYTES) : "memory");
            asm volatile("cp.async.bulk.commit_group;" ::: "memory");
        }
        // Drain stores before CTA exit (smem dealloc safety).
        asm volatile("cp.async.bulk.wait_group 0;" ::: "memory");
    }
}

extern "C" void kernel_launch(void* const* d_in, const int* in_sizes, int n_in,
                              void* d_out, int out_size)
{
    // metadata order: indices (int32, 8*2048), weight (float32, 50304*1024)
    const int*  indices = (const int*)d_in[0];
    const char* weight  = (const char*)d_in[1];
    char*       out     = (char*)d_out;

    const int rows = in_sizes[0];          // 16384
    gather_bulk_kernel<<<rows / ROWS_PER_CTA, 32>>>(indices, weight, out);
}

// round 5
// speedup vs baseline: 1.3814x; 1.3814x over previous
#include <cuda_runtime.h>
#include <cuda_bf16.h>
#include <cstdint>

// out[row, :] = weight[indices[row], :]
// rows = 16384, D = 1024 fp32 = 256 float4/row.
// 8 rows/CTA, 256 threads. Ordered asm-volatile loads force all 8 LDG.128
// to issue before any store (true MLP=8 per thread), then 8 streaming
// STG.128. Indices staged through smem.
constexpr int ROWS_PER_CTA = 8;

__device__ __forceinline__ float4 ldg_nc(const float4* p) {
    float4 v;
    asm volatile("ld.global.nc.v4.f32 {%0, %1, %2, %3}, [%4];"
                 : "=f"(v.x), "=f"(v.y), "=f"(v.z), "=f"(v.w)
                 : "l"(p));
    return v;
}

__device__ __forceinline__ void stg_cs(float4* p, float4 v) {
    asm volatile("st.global.cs.v4.f32 [%0], {%1, %2, %3, %4};"
                 :: "l"(p), "f"(v.x), "f"(v.y), "f"(v.z), "f"(v.w)
                 : "memory");
}

__global__ void __launch_bounds__(256)
gather_rows_kernel(const int* __restrict__ indices,
                   const float4* __restrict__ weight,
                   float4* __restrict__ out)
{
    __shared__ int sidx[ROWS_PER_CTA];

    const int base_row = blockIdx.x * ROWS_PER_CTA;
    if (threadIdx.x < ROWS_PER_CTA)
        sidx[threadIdx.x] = __ldg(&indices[base_row + threadIdx.x]);
    __syncthreads();

    const int tid = threadIdx.x;

    // Precompute all 8 source pointers, then issue 8 ordered loads
    // back-to-back: asm volatile ordering forbids interleaving stores,
    // so all 8 results are live at once -> real MLP = 8.
    const float4* src[ROWS_PER_CTA];
#pragma unroll
    for (int r = 0; r < ROWS_PER_CTA; r++)
        src[r] = weight + (size_t)sidx[r] * 256 + tid;

    float4 v[ROWS_PER_CTA];
#pragma unroll
    for (int r = 0; r < ROWS_PER_CTA; r++)
        v[r] = ldg_nc(src[r]);

    // Streaming stores: output is write-once; keep L2 for the weight table.
    float4* dst = out + (size_t)base_row * 256 + tid;
#pragma unroll
    for (int r = 0; r < ROWS_PER_CTA; r++) {
        stg_cs(dst, v[r]);
        dst += 256;
    }
}

extern "C" void kernel_launch(void* const* d_in, const int* in_sizes, int n_in,
                              void* d_out, int out_size)
{
    // metadata order: indices (int32, 8*2048), weight (float32, 50304*1024)
    const int*    indices = (const int*)d_in[0];
    const float4* weight  = (const float4*)d_in[1];
    float4*       out     = (float4*)d_out;

    const int rows = in_sizes[0];          // 16384
    gather_rows_kernel<<<rows / ROWS_PER_CTA, 256>>>(indices, weight, out);
}